// round 5
// baseline (speedup 1.0000x reference)
#include <cuda_runtime.h>

typedef unsigned long long u64;

// Fixed dims: B=8, N=256, NODE=128, EDGE=16, HID=256, MSG=128
#define MAXROWS 2048

__device__ u64   g_A[MAXROWS * 128];   // pairs: A = h@W1a + b1
__device__ u64   g_Bv[MAXROWS * 128];  // pairs: Bv = h@W1b
__device__ float g_S[MAXROWS * 256];   // per-row relu-sum
__device__ float g_deg[MAXROWS];

__device__ __forceinline__ u64 fma2(u64 a, u64 b, u64 c) {
    u64 d; asm("fma.rn.f32x2 %0,%1,%2,%3;" : "=l"(d) : "l"(a), "l"(b), "l"(c)); return d;
}
__device__ __forceinline__ u64 add2(u64 a, u64 b) {
    u64 d; asm("add.rn.f32x2 %0,%1,%2;" : "=l"(d) : "l"(a), "l"(b)); return d;
}
__device__ __forceinline__ u64 pack2(float x, float y) {
    u64 d; asm("mov.b64 %0,{%1,%2};" : "=l"(d) : "f"(x), "f"(y)); return d;
}
__device__ __forceinline__ float2 unpack2(u64 v) {
    float2 f; asm("mov.b64 {%0,%1},%2;" : "=f"(f.x), "=f"(f.y) : "l"(v)); return f;
}
__device__ __forceinline__ u64 dup2(float x) { return pack2(x, x); }
__device__ __forceinline__ u64 max2z(u64 a) {   // relu on a packed pair
    float2 f = unpack2(a);
    return pack2(fmaxf(f.x, 0.f), fmaxf(f.y, 0.f));
}

// ---------------------------------------------------------------------------
// Precompute A/Bv. Grid = (rows/8)*4: 8 rows x quarter of the q columns.
// Warp-per-row, thread owns one (row, q-pair) across all 128 k.
// ---------------------------------------------------------------------------
__global__ __launch_bounds__(256) void precompute_kernel(
    const float* __restrict__ h, const float* __restrict__ W1,
    const float* __restrict__ b1)
{
    __shared__ __align__(16) u64 hd[8][128];

    const int rg = blockIdx.x >> 2;     // row group of 8
    const int qq = blockIdx.x & 3;      // q quarter
    const int r0 = rg * 8;
    const int t  = threadIdx.x;

#pragma unroll
    for (int i = 0; i < 4; i++) {
        int idx = t + i * 256;          // 0..1023
        int r = idx >> 7, k = idx & 127;
        hd[r][k] = dup2(h[(size_t)(r0 + r) * 128 + k]);
    }
    __syncthreads();

    const int r = t >> 5;               // warp = row
    const int q = qq * 32 + (t & 31);   // q-pair index
    const u64* W1p = (const u64*)W1;

    u64 accA = 0ull, accB = 0ull;
#pragma unroll 8
    for (int k = 0; k < 128; k++) {
        u64 wa = W1p[(size_t)k * 128 + q];
        u64 wb = W1p[(size_t)(k + 128) * 128 + q];
        u64 hk = hd[r][k];
        accA = fma2(hk, wa, accA);
        accB = fma2(hk, wb, accB);
    }
    accA = add2(accA, ((const u64*)b1)[q]);
    g_A[(size_t)(r0 + r) * 128 + q]  = accA;
    g_Bv[(size_t)(r0 + r) * 128 + q] = accB;
}

// ---------------------------------------------------------------------------
// Main kernel: one (b,i) per block. 4j x 4h register tile, h-packed accs,
// software-pipelined Bv/jlist/cav prefetch. Emits S[256] and deg.
// ---------------------------------------------------------------------------
__global__ __launch_bounds__(256, 2) void mpnn_main(
    const float* __restrict__ adj, const float* __restrict__ ef,
    const float* __restrict__ W1)
{
    __shared__ __align__(16) float eT[16][256];   // transposed compacted edges
    __shared__ __align__(16) int   jlist[272];    // padded for prefetch
    __shared__ __align__(16) float cav[272];
    __shared__ int   wcnt[8];
    __shared__ float wsum[8];
    __shared__ int   s_m;
    __shared__ float s_deg;

    const int row = blockIdx.x;         // b*256 + i
    const int bb  = row >> 8;
    const int t   = threadIdx.x;
    const int jg  = t & 3;              // j-group (4 j's each)
    const int hg  = t >> 2;             // h-group: outputs 4hg..4hg+3
    const int w   = t >> 5, l = t & 31;

    // zero-init padded compaction arrays (prefetch reads up to mp+15 < 272)
    jlist[t] = 0; cav[t] = 0.f;
    if (t < 16) { jlist[256 + t] = 0; cav[256 + t] = 0.f; }

    // deterministic adjacency compaction
    const float av = adj[(size_t)row * 256 + t];
    const unsigned mask = __ballot_sync(0xffffffffu, av != 0.f);
    float ds = av;
#pragma unroll
    for (int off = 16; off; off >>= 1) ds += __shfl_xor_sync(0xffffffffu, ds, off);
    if (l == 0) { wcnt[w] = __popc(mask); wsum[w] = ds; }
    __syncthreads();
    if (t == 0) {
        int acc = 0; float d = 0.f;
#pragma unroll
        for (int i = 0; i < 8; i++) { int c = wcnt[i]; wcnt[i] = acc; acc += c; d += wsum[i]; }
        s_m = acc; s_deg = d;
    }

    // loop-invariant operands (issue LDGs early)
    u64 wA[16], wB[16];
    const u64* W1p = (const u64*)W1;
#pragma unroll
    for (int k = 0; k < 16; k++) {
        ulonglong2 wv = *(const ulonglong2*)(W1p + (size_t)(256 + k) * 128 + 2 * hg);
        wA[k] = wv.x; wB[k] = wv.y;
    }
    const ulonglong2 a2 = *(const ulonglong2*)(g_A + (size_t)row * 128 + 2 * hg);
    const u64* BvB = g_Bv + (size_t)(bb << 8) * 128;

    __syncthreads();
    const int   m   = s_m;
    const float deg = s_deg;
    const int   mp  = (m + 15) & ~15;

    if (av != 0.f) {
        int pos = wcnt[w] + __popc(mask & ((1u << l) - 1u));
        jlist[pos] = t;
        cav[pos]   = av;
    }
    __syncthreads();

    // stage compacted, transposed edge slice (zeros beyond m)
    if (t < mp) {
        if (t < m) {
            const int j = jlist[t];
            const float4* e4 = (const float4*)(ef + ((size_t)row * 256 + j) * 16);
            float4 v0 = e4[0], v1 = e4[1], v2 = e4[2], v3 = e4[3];
            eT[0][t]  = v0.x; eT[1][t]  = v0.y; eT[2][t]  = v0.z; eT[3][t]  = v0.w;
            eT[4][t]  = v1.x; eT[5][t]  = v1.y; eT[6][t]  = v1.z; eT[7][t]  = v1.w;
            eT[8][t]  = v2.x; eT[9][t]  = v2.y; eT[10][t] = v2.z; eT[11][t] = v2.w;
            eT[12][t] = v3.x; eT[13][t] = v3.y; eT[14][t] = v3.z; eT[15][t] = v3.w;
        } else {
#pragma unroll
            for (int k = 0; k < 16; k++) eT[k][t] = 0.f;
        }
    }
    __syncthreads();

    // pipelined mainloop
    int4   jl  = *(const int4*)&jlist[4 * jg];
    float4 avv = *(const float4*)&cav[4 * jg];
    ulonglong2 bv0 = *(const ulonglong2*)(BvB + (size_t)jl.x * 128 + 2 * hg);
    ulonglong2 bv1 = *(const ulonglong2*)(BvB + (size_t)jl.y * 128 + 2 * hg);
    ulonglong2 bv2 = *(const ulonglong2*)(BvB + (size_t)jl.z * 128 + 2 * hg);
    ulonglong2 bv3 = *(const ulonglong2*)(BvB + (size_t)jl.w * 128 + 2 * hg);

    u64 S0 = 0ull, S1 = 0ull;
#pragma unroll 1
    for (int base = 0; base < mp; base += 16) {
        // prefetch next iteration's indices + Bv (padded arrays make it safe)
        const int jbn = base + 16 + 4 * jg;
        const int4   jln = *(const int4*)&jlist[jbn];
        const float4 avn = *(const float4*)&cav[jbn];
        ulonglong2 nb0 = *(const ulonglong2*)(BvB + (size_t)jln.x * 128 + 2 * hg);
        ulonglong2 nb1 = *(const ulonglong2*)(BvB + (size_t)jln.y * 128 + 2 * hg);
        ulonglong2 nb2 = *(const ulonglong2*)(BvB + (size_t)jln.z * 128 + 2 * hg);
        ulonglong2 nb3 = *(const ulonglong2*)(BvB + (size_t)jln.w * 128 + 2 * hg);

        const int jb = base + 4 * jg;
        u64 a00 = a2.x, a01 = a2.y, a10 = a2.x, a11 = a2.y;
        u64 a20 = a2.x, a21 = a2.y, a30 = a2.x, a31 = a2.y;
#pragma unroll
        for (int k = 0; k < 16; k++) {
            float4 e = *(const float4*)&eT[k][jb];
            u64 e0 = dup2(e.x), e1 = dup2(e.y), e2 = dup2(e.z), e3 = dup2(e.w);
            a00 = fma2(e0, wA[k], a00); a01 = fma2(e0, wB[k], a01);
            a10 = fma2(e1, wA[k], a10); a11 = fma2(e1, wB[k], a11);
            a20 = fma2(e2, wA[k], a20); a21 = fma2(e2, wB[k], a21);
            a30 = fma2(e3, wA[k], a30); a31 = fma2(e3, wB[k], a31);
        }
        u64 d0 = dup2(avv.x), d1 = dup2(avv.y), d2 = dup2(avv.z), d3 = dup2(avv.w);
        S0 = fma2(d0, max2z(add2(a00, bv0.x)), S0);
        S1 = fma2(d0, max2z(add2(a01, bv0.y)), S1);
        S0 = fma2(d1, max2z(add2(a10, bv1.x)), S0);
        S1 = fma2(d1, max2z(add2(a11, bv1.y)), S1);
        S0 = fma2(d2, max2z(add2(a20, bv2.x)), S0);
        S1 = fma2(d2, max2z(add2(a21, bv2.y)), S1);
        S0 = fma2(d3, max2z(add2(a30, bv3.x)), S0);
        S1 = fma2(d3, max2z(add2(a31, bv3.y)), S1);

        jl = jln; avv = avn;
        bv0 = nb0; bv1 = nb1; bv2 = nb2; bv3 = nb3;
    }

    // reduce the 4 j-groups (adjacent lanes)
    float2 s0 = unpack2(S0), s1 = unpack2(S1);
#pragma unroll
    for (int off = 1; off <= 2; off <<= 1) {
        s0.x += __shfl_xor_sync(0xffffffffu, s0.x, off);
        s0.y += __shfl_xor_sync(0xffffffffu, s0.y, off);
        s1.x += __shfl_xor_sync(0xffffffffu, s1.x, off);
        s1.y += __shfl_xor_sync(0xffffffffu, s1.y, off);
    }
    if (jg == 0)
        *(float4*)(g_S + (size_t)row * 256 + 4 * hg) = make_float4(s0.x, s0.y, s1.x, s1.y);
    if (t == 0) g_deg[row] = deg;
}

// ---------------------------------------------------------------------------
// Update kernel: 8 rows per block (256 blocks). Three staged GEMMs with
// dup'd operands in smem; weight streams amortized 8x.
// ---------------------------------------------------------------------------
__global__ __launch_bounds__(256) void update_kernel(
    const float* __restrict__ h,  const float* __restrict__ W2,
    const float* __restrict__ b2, const float* __restrict__ U1,
    const float* __restrict__ c1, const float* __restrict__ U2,
    const float* __restrict__ c2, float* __restrict__ out)
{
    __shared__ __align__(16) u64 Sd[8][258];   // dup'd S; later dup'd uh
    __shared__ __align__(16) u64 xd[8][258];   // dup'd x = [h | agg]
    __shared__ float degs[8];

    const int t  = threadIdx.x;
    const int r0 = blockIdx.x * 8;

    {
        const int r = t >> 5, kl = t & 31;
        const float* Sp = g_S + (size_t)(r0 + r) * 256;
#pragma unroll
        for (int i = 0; i < 8; i++) Sd[r][kl + i * 32] = dup2(Sp[kl + i * 32]);
        const float* hp = h + (size_t)(r0 + r) * 128;
#pragma unroll
        for (int i = 0; i < 4; i++) xd[r][kl + i * 32] = dup2(hp[kl + i * 32]);
    }
    if (t < 8) degs[t] = g_deg[r0 + t];
    __syncthreads();

    // --- agg = S @ W2 + deg*b2 : 64 col-pairs x 4 row-groups(2 rows) ---
    {
        const int cp = t & 63, rr = t >> 6;
        const u64* W2p = (const u64*)W2;
        u64 acc0 = 0ull, acc1 = 0ull;
#pragma unroll 4
        for (int k = 0; k < 256; k += 2) {
            u64 w0 = W2p[(size_t)k * 64 + cp];
            u64 w1 = W2p[(size_t)(k + 1) * 64 + cp];
            ulonglong2 sA = *(const ulonglong2*)&Sd[rr * 2 + 0][k];
            ulonglong2 sB = *(const ulonglong2*)&Sd[rr * 2 + 1][k];
            acc0 = fma2(sA.x, w0, acc0); acc0 = fma2(sA.y, w1, acc0);
            acc1 = fma2(sB.x, w0, acc1); acc1 = fma2(sB.y, w1, acc1);
        }
        u64 b2p = ((const u64*)b2)[cp];
#pragma unroll
        for (int i = 0; i < 2; i++) {
            int r = rr * 2 + i;
            u64 g = fma2(dup2(degs[r]), b2p, i ? acc1 : acc0);
            float2 f = unpack2(g);
            xd[r][128 + 2 * cp]     = dup2(f.x);
            xd[r][128 + 2 * cp + 1] = dup2(f.y);
        }
    }
    __syncthreads();

    // --- uh = relu(x @ U1 + c1) : 128 col-pairs x 2 row-groups(4 rows) ---
    {
        const int cp = t & 127, rr = t >> 7;
        const u64* U1p = (const u64*)U1;
        u64 au[4] = {0ull, 0ull, 0ull, 0ull};
#pragma unroll 4
        for (int k = 0; k < 256; k += 2) {
            u64 w0 = U1p[(size_t)k * 128 + cp];
            u64 w1 = U1p[(size_t)(k + 1) * 128 + cp];
#pragma unroll
            for (int i = 0; i < 4; i++) {
                ulonglong2 x = *(const ulonglong2*)&xd[rr * 4 + i][k];
                au[i] = fma2(x.x, w0, au[i]);
                au[i] = fma2(x.y, w1, au[i]);
            }
        }
        u64 c1p = ((const u64*)c1)[cp];
        __syncthreads();   // Sd reads (stage 1) done before overwrite
#pragma unroll
        for (int i = 0; i < 4; i++) {
            u64 v = max2z(add2(au[i], c1p));
            float2 f = unpack2(v);
            Sd[rr * 4 + i][2 * cp]     = dup2(f.x);
            Sd[rr * 4 + i][2 * cp + 1] = dup2(f.y);
        }
    }
    __syncthreads();

    // --- out = uh @ U2 + c2 : 64 col-pairs x 4 row-groups(2 rows) ---
    {
        const int cp = t & 63, rr = t >> 6;
        const u64* U2p = (const u64*)U2;
        u64 ao0 = 0ull, ao1 = 0ull;
#pragma unroll 4
        for (int k = 0; k < 256; k += 2) {
            u64 w0 = U2p[(size_t)k * 64 + cp];
            u64 w1 = U2p[(size_t)(k + 1) * 64 + cp];
            ulonglong2 xA = *(const ulonglong2*)&Sd[rr * 2 + 0][k];
            ulonglong2 xB = *(const ulonglong2*)&Sd[rr * 2 + 1][k];
            ao0 = fma2(xA.x, w0, ao0); ao0 = fma2(xA.y, w1, ao0);
            ao1 = fma2(xB.x, w0, ao1); ao1 = fma2(xB.y, w1, ao1);
        }
        u64 c2p = ((const u64*)c2)[cp];
        ((u64*)out)[(size_t)(r0 + rr * 2 + 0) * 64 + cp] = add2(ao0, c2p);
        ((u64*)out)[(size_t)(r0 + rr * 2 + 1) * 64 + cp] = add2(ao1, c2p);
    }
}

extern "C" void kernel_launch(void* const* d_in, const int* in_sizes, int n_in,
                              void* d_out, int out_size)
{
    const float* h   = (const float*)d_in[0];
    const float* adj = (const float*)d_in[1];
    const float* ef  = (const float*)d_in[2];
    const float* W1  = (const float*)d_in[3];
    const float* b1  = (const float*)d_in[4];
    const float* W2  = (const float*)d_in[5];
    const float* b2  = (const float*)d_in[6];
    const float* U1  = (const float*)d_in[7];
    const float* c1  = (const float*)d_in[8];
    const float* U2  = (const float*)d_in[9];
    const float* c2  = (const float*)d_in[10];

    const int rows = in_sizes[0] / 128;   // B*N = 2048

    precompute_kernel<<<(rows / 8) * 4, 256>>>(h, W1, b1);
    mpnn_main<<<rows, 256>>>(adj, ef, W1);
    update_kernel<<<rows / 8, 256>>>(h, W2, b2, U1, c1, U2, c2, (float*)d_out);
}

// round 6
// speedup vs baseline: 1.1298x; 1.1298x over previous
#include <cuda_runtime.h>

typedef unsigned long long u64;

// Fixed dims: B=8, N=256, NODE=128, EDGE=16, HID=256, MSG=128
#define MAXROWS 2048

__device__ u64   g_A[MAXROWS * 128];   // pairs: A = h@W1a + b1
__device__ u64   g_Bv[MAXROWS * 128];  // pairs: Bv = h@W1b
__device__ float g_S[MAXROWS * 256];   // per-row relu-sum
__device__ float g_deg[MAXROWS];

__device__ __forceinline__ u64 fma2(u64 a, u64 b, u64 c) {
    u64 d; asm("fma.rn.f32x2 %0,%1,%2,%3;" : "=l"(d) : "l"(a), "l"(b), "l"(c)); return d;
}
__device__ __forceinline__ u64 add2(u64 a, u64 b) {
    u64 d; asm("add.rn.f32x2 %0,%1,%2;" : "=l"(d) : "l"(a), "l"(b)); return d;
}
__device__ __forceinline__ u64 pack2(float x, float y) {
    u64 d; asm("mov.b64 %0,{%1,%2};" : "=l"(d) : "f"(x), "f"(y)); return d;
}
__device__ __forceinline__ float2 unpack2(u64 v) {
    float2 f; asm("mov.b64 {%0,%1},%2;" : "=f"(f.x), "=f"(f.y) : "l"(v)); return f;
}
__device__ __forceinline__ u64 dup2(float x) { return pack2(x, x); }
__device__ __forceinline__ u64 max2z(u64 a) {   // relu on a packed pair
    float2 f = unpack2(a);
    return pack2(fmaxf(f.x, 0.f), fmaxf(f.y, 0.f));
}

// ---------------------------------------------------------------------------
// Precompute A/Bv. Grid = rows/4 = 512 blocks. Block: 4 rows x 128 q-pairs,
// 2-way k split. Each W1 load feeds 4 rows (register reuse), hd reads are
// warp-broadcast LDS.
// ---------------------------------------------------------------------------
__global__ __launch_bounds__(256) void precompute_kernel(
    const float* __restrict__ h, const float* __restrict__ W1,
    const float* __restrict__ b1)
{
    __shared__ __align__(16) u64 hd[4][128];
    __shared__ __align__(16) u64 bufA[4][128];
    __shared__ __align__(16) u64 bufB[4][128];

    const int r0 = blockIdx.x * 4;
    const int t  = threadIdx.x;

#pragma unroll
    for (int i = 0; i < 2; i++) {
        int id = t + i * 256;           // 0..511
        int r = id >> 7, k = id & 127;
        hd[r][k] = dup2(h[(size_t)(r0 + r) * 128 + k]);
    }
    __syncthreads();

    const int q = t & 127, s = t >> 7;
    const u64* W1p = (const u64*)W1;
    u64 aA[4] = {0ull, 0ull, 0ull, 0ull};
    u64 aB[4] = {0ull, 0ull, 0ull, 0ull};
    const int k0 = s * 64;
#pragma unroll 4
    for (int k = k0; k < k0 + 64; k++) {
        u64 wa = W1p[(size_t)k * 128 + q];
        u64 wb = W1p[(size_t)(k + 128) * 128 + q];
#pragma unroll
        for (int r = 0; r < 4; r++) {
            u64 hk = hd[r][k];
            aA[r] = fma2(hk, wa, aA[r]);
            aB[r] = fma2(hk, wb, aB[r]);
        }
    }
    if (s == 1) {
#pragma unroll
        for (int r = 0; r < 4; r++) { bufA[r][q] = aA[r]; bufB[r][q] = aB[r]; }
    }
    __syncthreads();
    if (s == 0) {
        u64 b1p = ((const u64*)b1)[q];
#pragma unroll
        for (int r = 0; r < 4; r++) {
            g_A[(size_t)(r0 + r) * 128 + q]  = add2(add2(aA[r], bufA[r][q]), b1p);
            g_Bv[(size_t)(r0 + r) * 128 + q] = add2(aB[r], bufB[r][q]);
        }
    }
}

// ---------------------------------------------------------------------------
// Main kernel: one (b,i) per block. 4j x 4h register tile, h-packed accs.
// Bv loads split-prefetched inside the iteration (2 before k-loop, 2 at k=8)
// so each pair gets ~128 fma2 of latency cover without extending all live
// ranges across the whole loop. Emits S[256] and deg.
// ---------------------------------------------------------------------------
__global__ __launch_bounds__(256, 2) void mpnn_main(
    const float* __restrict__ adj, const float* __restrict__ ef,
    const float* __restrict__ W1)
{
    __shared__ __align__(16) float eT[16][256];   // transposed compacted edges
    __shared__ __align__(16) int   jlist[256];
    __shared__ __align__(16) float cav[256];
    __shared__ int   wcnt[8];
    __shared__ float wsum[8];
    __shared__ int   s_m;
    __shared__ float s_deg;

    const int row = blockIdx.x;         // b*256 + i
    const int bb  = row >> 8;
    const int t   = threadIdx.x;
    const int jg  = t & 3;              // j-group (4 j's each)
    const int hg  = t >> 2;             // h-group: outputs 4hg..4hg+3
    const int w   = t >> 5, l = t & 31;

    // deterministic adjacency compaction
    const float av = adj[(size_t)row * 256 + t];
    const unsigned mask = __ballot_sync(0xffffffffu, av != 0.f);
    float ds = av;
#pragma unroll
    for (int off = 16; off; off >>= 1) ds += __shfl_xor_sync(0xffffffffu, ds, off);
    if (l == 0) { wcnt[w] = __popc(mask); wsum[w] = ds; }
    __syncthreads();
    if (t == 0) {
        int acc = 0; float d = 0.f;
#pragma unroll
        for (int i = 0; i < 8; i++) { int c = wcnt[i]; wcnt[i] = acc; acc += c; d += wsum[i]; }
        s_m = acc; s_deg = d;
    }

    // loop-invariant operands (issue LDGs early)
    u64 wA[16], wB[16];
    const u64* W1p = (const u64*)W1;
#pragma unroll
    for (int k = 0; k < 16; k++) {
        ulonglong2 wv = *(const ulonglong2*)(W1p + (size_t)(256 + k) * 128 + 2 * hg);
        wA[k] = wv.x; wB[k] = wv.y;
    }
    const ulonglong2 a2 = *(const ulonglong2*)(g_A + (size_t)row * 128 + 2 * hg);
    const u64* BvB = g_Bv + (size_t)(bb << 8) * 128;

    __syncthreads();
    const int   m   = s_m;
    const float deg = s_deg;
    const int   mp  = (m + 15) & ~15;

    if (av != 0.f) {
        int pos = wcnt[w] + __popc(mask & ((1u << l) - 1u));
        jlist[pos] = t;
        cav[pos]   = av;
    }
    if (t >= m && t < mp) { jlist[t] = 0; cav[t] = 0.f; }
    __syncthreads();

    // stage compacted, transposed edge slice (zeros beyond m)
    if (t < mp) {
        if (t < m) {
            const int j = jlist[t];
            const float4* e4 = (const float4*)(ef + ((size_t)row * 256 + j) * 16);
            float4 v0 = e4[0], v1 = e4[1], v2 = e4[2], v3 = e4[3];
            eT[0][t]  = v0.x; eT[1][t]  = v0.y; eT[2][t]  = v0.z; eT[3][t]  = v0.w;
            eT[4][t]  = v1.x; eT[5][t]  = v1.y; eT[6][t]  = v1.z; eT[7][t]  = v1.w;
            eT[8][t]  = v2.x; eT[9][t]  = v2.y; eT[10][t] = v2.z; eT[11][t] = v2.w;
            eT[12][t] = v3.x; eT[13][t] = v3.y; eT[14][t] = v3.z; eT[15][t] = v3.w;
        } else {
#pragma unroll
            for (int k = 0; k < 16; k++) eT[k][t] = 0.f;
        }
    }
    __syncthreads();

    u64 S0 = 0ull, S1 = 0ull;
#pragma unroll 1
    for (int base = 0; base < mp; base += 16) {
        const int jb = base + 4 * jg;
        const int4   jl  = *(const int4*)&jlist[jb];
        const float4 avv = *(const float4*)&cav[jb];

        // first half of Bv loads: covered by k=0..7 fma block
        const ulonglong2 bv0 = *(const ulonglong2*)(BvB + (size_t)jl.x * 128 + 2 * hg);
        const ulonglong2 bv1 = *(const ulonglong2*)(BvB + (size_t)jl.y * 128 + 2 * hg);

        u64 a00 = a2.x, a01 = a2.y, a10 = a2.x, a11 = a2.y;
        u64 a20 = a2.x, a21 = a2.y, a30 = a2.x, a31 = a2.y;
#pragma unroll
        for (int k = 0; k < 8; k++) {
            float4 e = *(const float4*)&eT[k][jb];
            u64 e0 = dup2(e.x), e1 = dup2(e.y), e2 = dup2(e.z), e3 = dup2(e.w);
            a00 = fma2(e0, wA[k], a00); a01 = fma2(e0, wB[k], a01);
            a10 = fma2(e1, wA[k], a10); a11 = fma2(e1, wB[k], a11);
            a20 = fma2(e2, wA[k], a20); a21 = fma2(e2, wB[k], a21);
            a30 = fma2(e3, wA[k], a30); a31 = fma2(e3, wB[k], a31);
        }
        // second half of Bv loads: covered by k=8..15 fma block
        const ulonglong2 bv2 = *(const ulonglong2*)(BvB + (size_t)jl.z * 128 + 2 * hg);
        const ulonglong2 bv3 = *(const ulonglong2*)(BvB + (size_t)jl.w * 128 + 2 * hg);
#pragma unroll
        for (int k = 8; k < 16; k++) {
            float4 e = *(const float4*)&eT[k][jb];
            u64 e0 = dup2(e.x), e1 = dup2(e.y), e2 = dup2(e.z), e3 = dup2(e.w);
            a00 = fma2(e0, wA[k], a00); a01 = fma2(e0, wB[k], a01);
            a10 = fma2(e1, wA[k], a10); a11 = fma2(e1, wB[k], a11);
            a20 = fma2(e2, wA[k], a20); a21 = fma2(e2, wB[k], a21);
            a30 = fma2(e3, wA[k], a30); a31 = fma2(e3, wB[k], a31);
        }

        u64 d0 = dup2(avv.x), d1 = dup2(avv.y), d2 = dup2(avv.z), d3 = dup2(avv.w);
        S0 = fma2(d0, max2z(add2(a00, bv0.x)), S0);
        S1 = fma2(d0, max2z(add2(a01, bv0.y)), S1);
        S0 = fma2(d1, max2z(add2(a10, bv1.x)), S0);
        S1 = fma2(d1, max2z(add2(a11, bv1.y)), S1);
        S0 = fma2(d2, max2z(add2(a20, bv2.x)), S0);
        S1 = fma2(d2, max2z(add2(a21, bv2.y)), S1);
        S0 = fma2(d3, max2z(add2(a30, bv3.x)), S0);
        S1 = fma2(d3, max2z(add2(a31, bv3.y)), S1);
    }

    // reduce the 4 j-groups (adjacent lanes)
    float2 s0 = unpack2(S0), s1 = unpack2(S1);
#pragma unroll
    for (int off = 1; off <= 2; off <<= 1) {
        s0.x += __shfl_xor_sync(0xffffffffu, s0.x, off);
        s0.y += __shfl_xor_sync(0xffffffffu, s0.y, off);
        s1.x += __shfl_xor_sync(0xffffffffu, s1.x, off);
        s1.y += __shfl_xor_sync(0xffffffffu, s1.y, off);
    }
    if (jg == 0)
        *(float4*)(g_S + (size_t)row * 256 + 4 * hg) = make_float4(s0.x, s0.y, s1.x, s1.y);
    if (t == 0) g_deg[row] = deg;
}

// ---------------------------------------------------------------------------
// Update kernel: 8 rows per block (256 blocks). Three staged GEMMs with
// dup'd operands in smem; weight streams amortized 8x.
// ---------------------------------------------------------------------------
__global__ __launch_bounds__(256) void update_kernel(
    const float* __restrict__ h,  const float* __restrict__ W2,
    const float* __restrict__ b2, const float* __restrict__ U1,
    const float* __restrict__ c1, const float* __restrict__ U2,
    const float* __restrict__ c2, float* __restrict__ out)
{
    __shared__ __align__(16) u64 Sd[8][258];   // dup'd S; later dup'd uh
    __shared__ __align__(16) u64 xd[8][258];   // dup'd x = [h | agg]
    __shared__ float degs[8];

    const int t  = threadIdx.x;
    const int r0 = blockIdx.x * 8;

    {
        const int r = t >> 5, kl = t & 31;
        const float* Sp = g_S + (size_t)(r0 + r) * 256;
#pragma unroll
        for (int i = 0; i < 8; i++) Sd[r][kl + i * 32] = dup2(Sp[kl + i * 32]);
        const float* hp = h + (size_t)(r0 + r) * 128;
#pragma unroll
        for (int i = 0; i < 4; i++) xd[r][kl + i * 32] = dup2(hp[kl + i * 32]);
    }
    if (t < 8) degs[t] = g_deg[r0 + t];
    __syncthreads();

    // --- agg = S @ W2 + deg*b2 : 64 col-pairs x 4 row-groups(2 rows) ---
    {
        const int cp = t & 63, rr = t >> 6;
        const u64* W2p = (const u64*)W2;
        u64 acc0 = 0ull, acc1 = 0ull;
#pragma unroll 4
        for (int k = 0; k < 256; k += 2) {
            u64 w0 = W2p[(size_t)k * 64 + cp];
            u64 w1 = W2p[(size_t)(k + 1) * 64 + cp];
            ulonglong2 sA = *(const ulonglong2*)&Sd[rr * 2 + 0][k];
            ulonglong2 sB = *(const ulonglong2*)&Sd[rr * 2 + 1][k];
            acc0 = fma2(sA.x, w0, acc0); acc0 = fma2(sA.y, w1, acc0);
            acc1 = fma2(sB.x, w0, acc1); acc1 = fma2(sB.y, w1, acc1);
        }
        u64 b2p = ((const u64*)b2)[cp];
#pragma unroll
        for (int i = 0; i < 2; i++) {
            int r = rr * 2 + i;
            u64 g = fma2(dup2(degs[r]), b2p, i ? acc1 : acc0);
            float2 f = unpack2(g);
            xd[r][128 + 2 * cp]     = dup2(f.x);
            xd[r][128 + 2 * cp + 1] = dup2(f.y);
        }
    }
    __syncthreads();

    // --- uh = relu(x @ U1 + c1) : 128 col-pairs x 2 row-groups(4 rows) ---
    {
        const int cp = t & 127, rr = t >> 7;
        const u64* U1p = (const u64*)U1;
        u64 au[4] = {0ull, 0ull, 0ull, 0ull};
#pragma unroll 4
        for (int k = 0; k < 256; k += 2) {
            u64 w0 = U1p[(size_t)k * 128 + cp];
            u64 w1 = U1p[(size_t)(k + 1) * 128 + cp];
#pragma unroll
            for (int i = 0; i < 4; i++) {
                ulonglong2 x = *(const ulonglong2*)&xd[rr * 4 + i][k];
                au[i] = fma2(x.x, w0, au[i]);
                au[i] = fma2(x.y, w1, au[i]);
            }
        }
        u64 c1p = ((const u64*)c1)[cp];
        __syncthreads();   // Sd reads (stage 1) done before overwrite
#pragma unroll
        for (int i = 0; i < 4; i++) {
            u64 v = max2z(add2(au[i], c1p));
            float2 f = unpack2(v);
            Sd[rr * 4 + i][2 * cp]     = dup2(f.x);
            Sd[rr * 4 + i][2 * cp + 1] = dup2(f.y);
        }
    }
    __syncthreads();

    // --- out = uh @ U2 + c2 : 64 col-pairs x 4 row-groups(2 rows) ---
    {
        const int cp = t & 63, rr = t >> 6;
        const u64* U2p = (const u64*)U2;
        u64 ao0 = 0ull, ao1 = 0ull;
#pragma unroll 4
        for (int k = 0; k < 256; k += 2) {
            u64 w0 = U2p[(size_t)k * 64 + cp];
            u64 w1 = U2p[(size_t)(k + 1) * 64 + cp];
            ulonglong2 xA = *(const ulonglong2*)&Sd[rr * 2 + 0][k];
            ulonglong2 xB = *(const ulonglong2*)&Sd[rr * 2 + 1][k];
            ao0 = fma2(xA.x, w0, ao0); ao0 = fma2(xA.y, w1, ao0);
            ao1 = fma2(xB.x, w0, ao1); ao1 = fma2(xB.y, w1, ao1);
        }
        u64 c2p = ((const u64*)c2)[cp];
        ((u64*)out)[(size_t)(r0 + rr * 2 + 0) * 64 + cp] = add2(ao0, c2p);
        ((u64*)out)[(size_t)(r0 + rr * 2 + 1) * 64 + cp] = add2(ao1, c2p);
    }
}

extern "C" void kernel_launch(void* const* d_in, const int* in_sizes, int n_in,
                              void* d_out, int out_size)
{
    const float* h   = (const float*)d_in[0];
    const float* adj = (const float*)d_in[1];
    const float* ef  = (const float*)d_in[2];
    const float* W1  = (const float*)d_in[3];
    const float* b1  = (const float*)d_in[4];
    const float* W2  = (const float*)d_in[5];
    const float* b2  = (const float*)d_in[6];
    const float* U1  = (const float*)d_in[7];
    const float* c1  = (const float*)d_in[8];
    const float* U2  = (const float*)d_in[9];
    const float* c2  = (const float*)d_in[10];

    const int rows = in_sizes[0] / 128;   // B*N = 2048

    precompute_kernel<<<rows / 4, 256>>>(h, W1, b1);
    mpnn_main<<<rows, 256>>>(adj, ef, W1);
    update_kernel<<<rows / 8, 256>>>(h, W2, b2, U1, c1, U2, c2, (float*)d_out);
}